// round 1
// baseline (speedup 1.0000x reference)
#include <cuda_runtime.h>

// RNN: B=4096, T=512, I=1, H=16, O=1
//   xp[b,t,h] = x[b,t]*w_ih[h] + b_ih[h] + b_hh[h]
//   h_t = tanh(xp_t + W_hh @ h_{t-1}),  h_0 = 0
//   out[b] = dot(h_T, w_fc) + b_fc
//
// Mapping: 16 lanes per batch element (lane j owns h[j]); 2 batch elems per
// warp -> 2048 warps total. Recurrence matvec via warp shuffles (width 16).

#define RNN_B 4096
#define RNN_T 512
#define RNN_H 16

__device__ __forceinline__ float tanh_fast(float x) {
    // tanh(x) = 1 - 2/(exp(2x)+1); saturates correctly at +/-inf, branch-free.
    float e = __expf(2.0f * x);                 // FMUL + MUFU.EX2
    return 1.0f - __fdividef(2.0f, e + 1.0f);   // FADD + MUFU.RCP + FMUL + FADD
}

__global__ __launch_bounds__(128) void rnn_scan_kernel(
    const float* __restrict__ x,      // [B, T, 1]
    const float* __restrict__ w_ih,   // [H, 1]
    const float* __restrict__ w_hh,   // [H, H]
    const float* __restrict__ b_ih,   // [H]
    const float* __restrict__ b_hh,   // [H]
    const float* __restrict__ w_fc,   // [1, H]
    const float* __restrict__ b_fc,   // [1]
    float* __restrict__ out)          // [B, 1]
{
    const int tid  = blockIdx.x * blockDim.x + threadIdx.x;
    const int warp = tid >> 5;
    const int lane = tid & 31;
    const int sub  = lane >> 4;   // which batch element within the warp (0/1)
    const int j    = lane & 15;   // hidden index owned by this lane

    const int b = warp * 2 + sub; // 2048 warps * 2 = 4096, always in range

    // Per-lane weights: row j of W_hh, w_ih[j], combined bias.
    float w[RNN_H];
    {
        const float4* w4 = reinterpret_cast<const float4*>(w_hh + j * RNN_H);
        float4 a0 = w4[0], a1 = w4[1], a2 = w4[2], a3 = w4[3];
        w[0]=a0.x; w[1]=a0.y; w[2]=a0.z; w[3]=a0.w;
        w[4]=a1.x; w[5]=a1.y; w[6]=a1.z; w[7]=a1.w;
        w[8]=a2.x; w[9]=a2.y; w[10]=a2.z; w[11]=a2.w;
        w[12]=a3.x; w[13]=a3.y; w[14]=a3.z; w[15]=a3.w;
    }
    const float wih  = w_ih[j];
    const float bias = b_ih[j] + b_hh[j];

    const float4* x4 = reinterpret_cast<const float4*>(x + (long)b * RNN_T);

    float h = 0.0f;

    #pragma unroll 1
    for (int t4 = 0; t4 < RNN_T / 4; t4++) {
        const float4 xv = x4[t4];
        float xs[4] = {xv.x, xv.y, xv.z, xv.w};
        #pragma unroll
        for (int s = 0; s < 4; s++) {
            float acc = fmaf(xs[s], wih, bias);
            #pragma unroll
            for (int k = 0; k < RNN_H; k++) {
                // width=16: srcLane k resolves within this 16-lane group
                float hk = __shfl_sync(0xffffffffu, h, k, 16);
                acc = fmaf(w[k], hk, acc);
            }
            h = tanh_fast(acc);
        }
    }

    // out[b] = sum_j h[j] * w_fc[j] + b_fc
    float v = h * w_fc[j];
    #pragma unroll
    for (int off = 8; off; off >>= 1)
        v += __shfl_xor_sync(0xffffffffu, v, off, 16);
    if (j == 0)
        out[b] = v + b_fc[0];
}

extern "C" void kernel_launch(void* const* d_in, const int* in_sizes, int n_in,
                              void* d_out, int out_size) {
    const float* x    = (const float*)d_in[0];
    const float* w_ih = (const float*)d_in[1];
    const float* w_hh = (const float*)d_in[2];
    const float* b_ih = (const float*)d_in[3];
    const float* b_hh = (const float*)d_in[4];
    const float* w_fc = (const float*)d_in[5];
    const float* b_fc = (const float*)d_in[6];
    float* out = (float*)d_out;

    // 4096 batch elems * 16 lanes = 65536 threads = 2048 warps
    const int threads = 128;
    const int blocks  = (RNN_B * RNN_H) / threads; // 512
    rnn_scan_kernel<<<blocks, threads>>>(x, w_ih, w_hh, b_ih, b_hh, w_fc, b_fc, out);
}

// round 2
// speedup vs baseline: 1.4613x; 1.4613x over previous
#include <cuda_runtime.h>

// RNN: B=4096, T=512, I=1, H=16, O=1
//   a_t[j] = x_t*w_ih[j] + b_ih[j] + b_hh[j] + sum_k w_hh[j][k]*h_{t-1}[k]
//   h_t = tanh(a_t),  h_0 = 0;  out[b] = dot(h_T, w_fc) + b_fc
//
// Mapping: 16 lanes per batch element (lane j owns unit j); 2 batch elems
// per warp -> 2048 warps. Recurrence carried in r-space:
//   r = 1/(1 + 2^(K*a)),  K = 2*log2(e),  h = 1 - 2r  (h0=0 -> r0=0.5)
// Folding (1-2r) and K into per-lane constants:
//   acc = biasK + x*wihK + sum_k wfold[k]*r[k]
//   wihK  = K*w_ih[j];  biasK = K*(b_ih[j]+b_hh[j]+sum_k w_hh[j][k])
//   wfold[k] = -2K*w_hh[j][k]
// Per step: 16 front-loaded SHFLs of r, 17-FMA tree (4 accumulators),
// EX2 + FADD + RCP. No tanh epilogue on the critical path.

#define RNN_B 4096
#define RNN_T 512
#define RNN_H 16

__device__ __forceinline__ float ex2_approx(float x) {
    float y;
    asm("ex2.approx.f32 %0, %1;" : "=f"(y) : "f"(x));
    return y;
}
__device__ __forceinline__ float rcp_approx(float x) {
    float y;
    asm("rcp.approx.f32 %0, %1;" : "=f"(y) : "f"(x));
    return y;
}

__global__ __launch_bounds__(128) void rnn_scan_kernel(
    const float* __restrict__ x,      // [B, T, 1]
    const float* __restrict__ w_ih,   // [H, 1]
    const float* __restrict__ w_hh,   // [H, H]
    const float* __restrict__ b_ih,   // [H]
    const float* __restrict__ b_hh,   // [H]
    const float* __restrict__ w_fc,   // [1, H]
    const float* __restrict__ b_fc,   // [1]
    float* __restrict__ out)          // [B, 1]
{
    const int tid  = blockIdx.x * blockDim.x + threadIdx.x;
    const int warp = tid >> 5;
    const int lane = tid & 31;
    const int sub  = lane >> 4;   // batch element within warp (0/1)
    const int j    = lane & 15;   // hidden unit owned by this lane

    const int b = warp * 2 + sub; // always < 4096

    const float K = 2.8853900817779268f; // 2*log2(e)

    // Per-lane folded constants.
    float wfold[RNN_H];
    float wsum = 0.0f;
    {
        const float4* w4 = reinterpret_cast<const float4*>(w_hh + j * RNN_H);
        float4 a0 = w4[0], a1 = w4[1], a2 = w4[2], a3 = w4[3];
        float wr[RNN_H] = {a0.x,a0.y,a0.z,a0.w, a1.x,a1.y,a1.z,a1.w,
                           a2.x,a2.y,a2.z,a2.w, a3.x,a3.y,a3.z,a3.w};
        #pragma unroll
        for (int k = 0; k < RNN_H; k++) {
            wsum += wr[k];
            wfold[k] = -2.0f * K * wr[k];
        }
    }
    const float wihK  = K * w_ih[j];
    const float biasK = K * (b_ih[j] + b_hh[j] + wsum);

    const float4* x4 = reinterpret_cast<const float4*>(x + (long)b * RNN_T);

    float r = 0.5f;  // h0 = 0  <=>  r0 = 0.5

    #pragma unroll 1
    for (int t4 = 0; t4 < RNN_T / 4; t4++) {
        const float4 xv = x4[t4];
        float xs[4] = {xv.x, xv.y, xv.z, xv.w};
        #pragma unroll
        for (int s = 0; s < 4; s++) {
            // Front-load all 16 independent shuffles of r.
            float rv[RNN_H];
            #pragma unroll
            for (int k = 0; k < RNN_H; k++)
                rv[k] = __shfl_sync(0xffffffffu, r, k, 16);

            // 4-way accumulation tree.
            float a0 = fmaf(xs[s], wihK, biasK);
            float a1 = wfold[1] * rv[1];
            float a2 = wfold[2] * rv[2];
            float a3 = wfold[3] * rv[3];
            a0 = fmaf(wfold[0], rv[0], a0);
            #pragma unroll
            for (int k = 4; k < RNN_H; k += 4) {
                a0 = fmaf(wfold[k + 0], rv[k + 0], a0);
                a1 = fmaf(wfold[k + 1], rv[k + 1], a1);
                a2 = fmaf(wfold[k + 2], rv[k + 2], a2);
                a3 = fmaf(wfold[k + 3], rv[k + 3], a3);
            }
            float acc = (a0 + a1) + (a2 + a3);

            // r = 1/(1 + 2^acc)
            r = rcp_approx(1.0f + ex2_approx(acc));
        }
    }

    // h_T = 1 - 2r; out[b] = sum_j h_j * w_fc[j] + b_fc
    float h = fmaf(-2.0f, r, 1.0f);
    float v = h * w_fc[j];
    #pragma unroll
    for (int off = 8; off; off >>= 1)
        v += __shfl_xor_sync(0xffffffffu, v, off, 16);
    if (j == 0)
        out[b] = v + b_fc[0];
}

extern "C" void kernel_launch(void* const* d_in, const int* in_sizes, int n_in,
                              void* d_out, int out_size) {
    const float* x    = (const float*)d_in[0];
    const float* w_ih = (const float*)d_in[1];
    const float* w_hh = (const float*)d_in[2];
    const float* b_ih = (const float*)d_in[3];
    const float* b_hh = (const float*)d_in[4];
    const float* w_fc = (const float*)d_in[5];
    const float* b_fc = (const float*)d_in[6];
    float* out = (float*)d_out;

    const int threads = 128;
    const int blocks  = (RNN_B * RNN_H) / threads; // 512 blocks, 2048 warps
    rnn_scan_kernel<<<blocks, threads>>>(x, w_ih, w_hh, b_ih, b_hh, w_fc, b_fc, out);
}